// round 2
// baseline (speedup 1.0000x reference)
#include <cuda_runtime.h>

#define L_MAX   2048
#define BATCH   64
#define DDIM    256
#define CCH     512
#define NCHUNK  16
#define ROWS_PER_CHUNK (L_MAX / NCHUNK)   // 128
#define ROWS_PER_WARP  (ROWS_PER_CHUNK / 8) // 16

// ---- scratch (no allocations allowed) ----
__device__ float g_hq[BATCH * DDIM];          // ht_query @ W_query^T + b_att_past
__device__ float g_M[3 * DDIM];               // fused conv*fc weights
__device__ float g_hardU[L_MAX * BATCH];      // unnormalized hard mask
__device__ float g_part[BATCH * NCHUNK * DDIM]; // per-(b,chunk) ct partials
__device__ float g_denp[BATCH * NCHUNK];      // per-(b,chunk) hard sums

// accurate-enough tanh: ~1e-7 abs error, 2 MUFU + few FMA
__device__ __forceinline__ float ftanh(float x) {
    float e = __expf(2.0f * x);
    return 1.0f - __fdividef(2.0f, e + 1.0f);
}

// ---------------------------------------------------------------------------
// Kernel 1: prep.  grid=(BATCH), block=(DDIM)
//   g_hq[b,d] = sum_e ht[b,e]*Wq[d,e] + bap[d]
//   g_M[k,d]  = sum_c Wap[d,c]*Wc[c,0,k]   (block 0 only)
// ---------------------------------------------------------------------------
__global__ __launch_bounds__(DDIM) void prep_kernel(
    const float* __restrict__ ht, const float* __restrict__ Wq,
    const float* __restrict__ Wap, const float* __restrict__ Wc,
    const float* __restrict__ bap)
{
    __shared__ float s_ht[DDIM];
    int b = blockIdx.x, d = threadIdx.x;
    s_ht[d] = ht[b * DDIM + d];
    __syncthreads();

    const float4* wrow = reinterpret_cast<const float4*>(Wq + (size_t)d * DDIM);
    float a0 = 0.f, a1 = 0.f, a2 = 0.f, a3 = 0.f;
#pragma unroll 8
    for (int e4 = 0; e4 < DDIM / 4; e4++) {
        float4 w = wrow[e4];
        a0 += s_ht[e4 * 4 + 0] * w.x;
        a1 += s_ht[e4 * 4 + 1] * w.y;
        a2 += s_ht[e4 * 4 + 2] * w.z;
        a3 += s_ht[e4 * 4 + 3] * w.w;
    }
    g_hq[b * DDIM + d] = (a0 + a1) + (a2 + a3) + bap[d];

    if (b == 0) {
        float m0 = 0.f, m1 = 0.f, m2 = 0.f;
        const float* wr = Wap + (size_t)d * CCH;
#pragma unroll 4
        for (int c = 0; c < CCH; c++) {
            float wv = wr[c];
            m0 += wv * Wc[c * 3 + 0];
            m1 += wv * Wc[c * 3 + 1];
            m2 += wv * Wc[c * 3 + 2];
        }
        g_M[0 * DDIM + d] = m0;
        g_M[1 * DDIM + d] = m1;
        g_M[2 * DDIM + d] = m2;
    }
}

// ---------------------------------------------------------------------------
// Kernel 2: main.  grid=(NCHUNK, BATCH), block=256 (8 warps).
// Warp handles 16 rows (l). Per row: score -> hardU -> conditional ct accum.
// Deterministic: warp partials -> shared -> ordered sum -> g_part.
// ---------------------------------------------------------------------------
__global__ __launch_bounds__(256) void main_kernel(
    const float* __restrict__ ctx_val, const float* __restrict__ ctx_key,
    const float* __restrict__ ctx_mask, const float* __restrict__ past,
    const float* __restrict__ W_attn, const float* __restrict__ b_attn)
{
    __shared__ float s_acc[8 * DDIM];
    __shared__ float s_cnt[8];

    int b = blockIdx.y, chunk = blockIdx.x;
    int w = threadIdx.x >> 5, lane = threadIdx.x & 31;
    int d0 = lane * 4;        // d in [0,128)
    int d1 = 128 + lane * 4;  // d in [128,256)

    float4 hq0 = *reinterpret_cast<const float4*>(&g_hq[b * DDIM + d0]);
    float4 hq1 = *reinterpret_cast<const float4*>(&g_hq[b * DDIM + d1]);
    float4 M00 = *reinterpret_cast<const float4*>(&g_M[d0]);
    float4 M01 = *reinterpret_cast<const float4*>(&g_M[d1]);
    float4 M10 = *reinterpret_cast<const float4*>(&g_M[DDIM + d0]);
    float4 M11 = *reinterpret_cast<const float4*>(&g_M[DDIM + d1]);
    float4 M20 = *reinterpret_cast<const float4*>(&g_M[2 * DDIM + d0]);
    float4 M21 = *reinterpret_cast<const float4*>(&g_M[2 * DDIM + d1]);
    float4 Wa0 = *reinterpret_cast<const float4*>(&W_attn[d0]);
    float4 Wa1 = *reinterpret_cast<const float4*>(&W_attn[d1]);
    float ba = b_attn[0];

    float4 acc0 = make_float4(0.f, 0.f, 0.f, 0.f);
    float4 acc1 = make_float4(0.f, 0.f, 0.f, 0.f);
    float hsum = 0.f;

    int lbase = chunk * ROWS_PER_CHUNK + w * ROWS_PER_WARP;
    for (int r = 0; r < ROWS_PER_WARP; r++) {
        int l = lbase + r;
        size_t row = ((size_t)l * BATCH + b) * DDIM;
        float4 k0 = *reinterpret_cast<const float4*>(ctx_key + row + d0);
        float4 k1 = *reinterpret_cast<const float4*>(ctx_key + row + d1);

        float pm = (l > 0)         ? past[b * L_MAX + l - 1] : 0.f;
        float p0 =                   past[b * L_MAX + l];
        float pp = (l < L_MAX - 1) ? past[b * L_MAX + l + 1] : 0.f;

        float s;
        s  = Wa0.x * ftanh(k0.x + hq0.x + pm * M00.x + p0 * M10.x + pp * M20.x);
        s += Wa0.y * ftanh(k0.y + hq0.y + pm * M00.y + p0 * M10.y + pp * M20.y);
        s += Wa0.z * ftanh(k0.z + hq0.z + pm * M00.z + p0 * M10.z + pp * M20.z);
        s += Wa0.w * ftanh(k0.w + hq0.w + pm * M00.w + p0 * M10.w + pp * M20.w);
        s += Wa1.x * ftanh(k1.x + hq1.x + pm * M01.x + p0 * M11.x + pp * M21.x);
        s += Wa1.y * ftanh(k1.y + hq1.y + pm * M01.y + p0 * M11.y + pp * M21.y);
        s += Wa1.z * ftanh(k1.z + hq1.z + pm * M01.z + p0 * M11.z + pp * M21.z);
        s += Wa1.w * ftanh(k1.w + hq1.w + pm * M01.w + p0 * M11.w + pp * M21.w);

#pragma unroll
        for (int off = 16; off; off >>= 1)
            s += __shfl_xor_sync(0xffffffffu, s, off);

        float score = s + ba;
        float h = (score >= 0.f) ? ctx_mask[l * BATCH + b] : 0.f;
        if (lane == 0) g_hardU[l * BATCH + b] = h;
        hsum += h;

        if (h != 0.f) {  // warp-uniform branch: skip ctx_val row entirely
            float4 v0 = *reinterpret_cast<const float4*>(ctx_val + row + d0);
            float4 v1 = *reinterpret_cast<const float4*>(ctx_val + row + d1);
            acc0.x += h * v0.x; acc0.y += h * v0.y;
            acc0.z += h * v0.z; acc0.w += h * v0.w;
            acc1.x += h * v1.x; acc1.y += h * v1.y;
            acc1.z += h * v1.z; acc1.w += h * v1.w;
        }
    }

    *reinterpret_cast<float4*>(&s_acc[w * DDIM + d0]) = acc0;
    *reinterpret_cast<float4*>(&s_acc[w * DDIM + d1]) = acc1;
    if (lane == 0) s_cnt[w] = hsum;
    __syncthreads();

    int d = threadIdx.x;
    float p = 0.f;
#pragma unroll
    for (int ww = 0; ww < 8; ww++) p += s_acc[ww * DDIM + d];
    g_part[((size_t)b * NCHUNK + chunk) * DDIM + d] = p;

    if (threadIdx.x == 0) {
        float c = 0.f;
#pragma unroll
        for (int ww = 0; ww < 8; ww++) c += s_cnt[ww];
        g_denp[b * NCHUNK + chunk] = c;
    }
}

// ---------------------------------------------------------------------------
// Kernel 3: finish.  Normalize and write output = concat(ct.flat, hard.flat)
// ---------------------------------------------------------------------------
__global__ __launch_bounds__(256) void finish_kernel(float* __restrict__ out)
{
    int i = blockIdx.x * blockDim.x + threadIdx.x;
    if (i < BATCH * DDIM) {
        int b = i >> 8;
        int d = i & (DDIM - 1);
        float den = 0.f;
#pragma unroll
        for (int c = 0; c < NCHUNK; c++) den += g_denp[b * NCHUNK + c];
        float ct = 0.f;
#pragma unroll
        for (int c = 0; c < NCHUNK; c++)
            ct += g_part[((size_t)b * NCHUNK + c) * DDIM + d];
        out[i] = ct / (den + 1e-10f);
    } else if (i < BATCH * DDIM + L_MAX * BATCH) {
        int j = i - BATCH * DDIM;
        int b = j & (BATCH - 1);
        float den = 0.f;
#pragma unroll
        for (int c = 0; c < NCHUNK; c++) den += g_denp[b * NCHUNK + c];
        out[i] = g_hardU[j] / (den + 1e-10f);
    }
}

// ---------------------------------------------------------------------------
extern "C" void kernel_launch(void* const* d_in, const int* in_sizes, int n_in,
                              void* d_out, int out_size)
{
    (void)in_sizes; (void)n_in; (void)out_size;
    const float* ctx_val  = (const float*)d_in[0];
    const float* ctx_key  = (const float*)d_in[1];
    const float* ctx_mask = (const float*)d_in[2];
    const float* past     = (const float*)d_in[3];  // attention_past (B,1,L)
    const float* ht       = (const float*)d_in[4];
    const float* Wc       = (const float*)d_in[5];  // (512,1,3)
    const float* Wq       = (const float*)d_in[6];  // (256,256)
    const float* Wap      = (const float*)d_in[7];  // (256,512)
    const float* bap      = (const float*)d_in[8];  // (256,)
    const float* Wattn    = (const float*)d_in[9];  // (1,256)
    const float* battn    = (const float*)d_in[10]; // (1,)
    float* out = (float*)d_out;

    prep_kernel<<<BATCH, DDIM>>>(ht, Wq, Wap, Wc, bap);

    dim3 grid(NCHUNK, BATCH);
    main_kernel<<<grid, 256>>>(ctx_val, ctx_key, ctx_mask, past, Wattn, battn);

    int total = BATCH * DDIM + L_MAX * BATCH;
    finish_kernel<<<(total + 255) / 256, 256>>>(out);
}

// round 3
// speedup vs baseline: 2.1315x; 2.1315x over previous
#include <cuda_runtime.h>

#define L_MAX   2048
#define BATCH   64
#define DDIM    256
#define CCH     512
#define NCHUNK  16
#define ROWS_PER_CHUNK (L_MAX / NCHUNK)   // 128
#define ROWS_PER_WARP  (ROWS_PER_CHUNK / 8) // 16

// hq warps: one per (b,d) output = 64*256 = 16384 warps = 2048 blocks of 8 warps
#define HQ_BLOCKS 2048
// M warps: one per (k,d) output = 3*256 = 768 warps = 96 blocks
#define M_BLOCKS  96

// ---- scratch (no allocations allowed) ----
__device__ float g_hq[BATCH * DDIM];          // ht_query @ W_query^T + b_att_past
__device__ float g_M[3 * DDIM];               // fused conv*fc weights
__device__ float g_hardU[L_MAX * BATCH];      // unnormalized hard mask
__device__ float g_part[BATCH * NCHUNK * DDIM]; // per-(b,chunk) ct partials
__device__ float g_denp[BATCH * NCHUNK];      // per-(b,chunk) hard sums

// accurate-enough tanh: ~1e-7 abs error, 2 MUFU + few FMA
__device__ __forceinline__ float ftanh(float x) {
    float e = __expf(2.0f * x);
    return 1.0f - __fdividef(2.0f, e + 1.0f);
}

// ---------------------------------------------------------------------------
// Kernel 1: prep (warp-per-output, fully coalesced).
//   blocks [0, HQ_BLOCKS):        g_hq[b,d] = ht[b,:]·Wq[d,:] + bap[d]
//   blocks [HQ_BLOCKS, +M_BLOCKS): g_M[k,d] = Wap[d,:]·Wc[:,0,k]
// ---------------------------------------------------------------------------
__global__ __launch_bounds__(256) void prep_kernel(
    const float* __restrict__ ht, const float* __restrict__ Wq,
    const float* __restrict__ Wap, const float* __restrict__ Wc,
    const float* __restrict__ bap)
{
    int warp = threadIdx.x >> 5, lane = threadIdx.x & 31;

    if (blockIdx.x < HQ_BLOCKS) {
        int gw = blockIdx.x * 8 + warp;       // [0, 16384)
        int b = gw >> 8;
        int d = gw & 255;
        const float* htr = ht + b * DDIM;
        const float* wqr = Wq + (size_t)d * DDIM;
        float a = 0.f;
#pragma unroll
        for (int i = 0; i < DDIM / 32; i++) { // 8 coalesced iterations
            int e = lane + 32 * i;
            a += htr[e] * wqr[e];
        }
#pragma unroll
        for (int off = 16; off; off >>= 1)
            a += __shfl_xor_sync(0xffffffffu, a, off);
        if (lane == 0) g_hq[b * DDIM + d] = a + bap[d];
    } else {
        int gw = (blockIdx.x - HQ_BLOCKS) * 8 + warp;  // [0, 768)
        int d = gw >> 2 ? 0 : 0; // placeholder removed below
        (void)d;
        int dd = gw / 3;
        int k  = gw % 3;
        const float* wr = Wap + (size_t)dd * CCH;
        float m = 0.f;
#pragma unroll
        for (int i = 0; i < CCH / 32; i++) {  // 16 coalesced iterations
            int c = lane + 32 * i;
            m += wr[c] * Wc[c * 3 + k];
        }
#pragma unroll
        for (int off = 16; off; off >>= 1)
            m += __shfl_xor_sync(0xffffffffu, m, off);
        if (lane == 0) g_M[k * DDIM + dd] = m;
    }
}

// ---------------------------------------------------------------------------
// Kernel 2: main.  grid=(NCHUNK, BATCH), block=256 (8 warps).
// Warp handles 16 rows (l). Per row: score -> hardU -> conditional ct accum.
// Deterministic: warp partials -> shared -> ordered sum -> g_part.
// ---------------------------------------------------------------------------
__global__ __launch_bounds__(256) void main_kernel(
    const float* __restrict__ ctx_val, const float* __restrict__ ctx_key,
    const float* __restrict__ ctx_mask, const float* __restrict__ past,
    const float* __restrict__ W_attn, const float* __restrict__ b_attn)
{
    __shared__ float s_acc[8 * DDIM];
    __shared__ float s_cnt[8];

    int b = blockIdx.y, chunk = blockIdx.x;
    int w = threadIdx.x >> 5, lane = threadIdx.x & 31;
    int d0 = lane * 4;        // d in [0,128)
    int d1 = 128 + lane * 4;  // d in [128,256)

    float4 hq0 = *reinterpret_cast<const float4*>(&g_hq[b * DDIM + d0]);
    float4 hq1 = *reinterpret_cast<const float4*>(&g_hq[b * DDIM + d1]);
    float4 M00 = *reinterpret_cast<const float4*>(&g_M[d0]);
    float4 M01 = *reinterpret_cast<const float4*>(&g_M[d1]);
    float4 M10 = *reinterpret_cast<const float4*>(&g_M[DDIM + d0]);
    float4 M11 = *reinterpret_cast<const float4*>(&g_M[DDIM + d1]);
    float4 M20 = *reinterpret_cast<const float4*>(&g_M[2 * DDIM + d0]);
    float4 M21 = *reinterpret_cast<const float4*>(&g_M[2 * DDIM + d1]);
    float4 Wa0 = *reinterpret_cast<const float4*>(&W_attn[d0]);
    float4 Wa1 = *reinterpret_cast<const float4*>(&W_attn[d1]);
    float ba = b_attn[0];

    float4 acc0 = make_float4(0.f, 0.f, 0.f, 0.f);
    float4 acc1 = make_float4(0.f, 0.f, 0.f, 0.f);
    float hsum = 0.f;

    int lbase = chunk * ROWS_PER_CHUNK + w * ROWS_PER_WARP;
    for (int r = 0; r < ROWS_PER_WARP; r++) {
        int l = lbase + r;
        size_t row = ((size_t)l * BATCH + b) * DDIM;
        float4 k0 = *reinterpret_cast<const float4*>(ctx_key + row + d0);
        float4 k1 = *reinterpret_cast<const float4*>(ctx_key + row + d1);

        float pm = (l > 0)         ? past[b * L_MAX + l - 1] : 0.f;
        float p0 =                   past[b * L_MAX + l];
        float pp = (l < L_MAX - 1) ? past[b * L_MAX + l + 1] : 0.f;

        float s;
        s  = Wa0.x * ftanh(k0.x + hq0.x + pm * M00.x + p0 * M10.x + pp * M20.x);
        s += Wa0.y * ftanh(k0.y + hq0.y + pm * M00.y + p0 * M10.y + pp * M20.y);
        s += Wa0.z * ftanh(k0.z + hq0.z + pm * M00.z + p0 * M10.z + pp * M20.z);
        s += Wa0.w * ftanh(k0.w + hq0.w + pm * M00.w + p0 * M10.w + pp * M20.w);
        s += Wa1.x * ftanh(k1.x + hq1.x + pm * M01.x + p0 * M11.x + pp * M21.x);
        s += Wa1.y * ftanh(k1.y + hq1.y + pm * M01.y + p0 * M11.y + pp * M21.y);
        s += Wa1.z * ftanh(k1.z + hq1.z + pm * M01.z + p0 * M11.z + pp * M21.z);
        s += Wa1.w * ftanh(k1.w + hq1.w + pm * M01.w + p0 * M11.w + pp * M21.w);

#pragma unroll
        for (int off = 16; off; off >>= 1)
            s += __shfl_xor_sync(0xffffffffu, s, off);

        float score = s + ba;
        float h = (score >= 0.f) ? ctx_mask[l * BATCH + b] : 0.f;
        if (lane == 0) g_hardU[l * BATCH + b] = h;
        hsum += h;

        if (h != 0.f) {  // warp-uniform branch: skip ctx_val row entirely
            float4 v0 = *reinterpret_cast<const float4*>(ctx_val + row + d0);
            float4 v1 = *reinterpret_cast<const float4*>(ctx_val + row + d1);
            acc0.x += h * v0.x; acc0.y += h * v0.y;
            acc0.z += h * v0.z; acc0.w += h * v0.w;
            acc1.x += h * v1.x; acc1.y += h * v1.y;
            acc1.z += h * v1.z; acc1.w += h * v1.w;
        }
    }

    *reinterpret_cast<float4*>(&s_acc[w * DDIM + d0]) = acc0;
    *reinterpret_cast<float4*>(&s_acc[w * DDIM + d1]) = acc1;
    if (lane == 0) s_cnt[w] = hsum;
    __syncthreads();

    int d = threadIdx.x;
    float p = 0.f;
#pragma unroll
    for (int ww = 0; ww < 8; ww++) p += s_acc[ww * DDIM + d];
    g_part[((size_t)b * NCHUNK + chunk) * DDIM + d] = p;

    if (threadIdx.x == 0) {
        float c = 0.f;
#pragma unroll
        for (int ww = 0; ww < 8; ww++) c += s_cnt[ww];
        g_denp[b * NCHUNK + chunk] = c;
    }
}

// ---------------------------------------------------------------------------
// Kernel 3: finish.  Normalize and write output = concat(ct.flat, hard.flat)
// ---------------------------------------------------------------------------
__global__ __launch_bounds__(256) void finish_kernel(float* __restrict__ out)
{
    int i = blockIdx.x * blockDim.x + threadIdx.x;
    if (i < BATCH * DDIM) {
        int b = i >> 8;
        int d = i & (DDIM - 1);
        float den = 0.f;
#pragma unroll
        for (int c = 0; c < NCHUNK; c++) den += g_denp[b * NCHUNK + c];
        float ct = 0.f;
#pragma unroll
        for (int c = 0; c < NCHUNK; c++)
            ct += g_part[((size_t)b * NCHUNK + c) * DDIM + d];
        out[i] = ct / (den + 1e-10f);
    } else if (i < BATCH * DDIM + L_MAX * BATCH) {
        int j = i - BATCH * DDIM;
        int b = j & (BATCH - 1);
        float den = 0.f;
#pragma unroll
        for (int c = 0; c < NCHUNK; c++) den += g_denp[b * NCHUNK + c];
        out[i] = g_hardU[j] / (den + 1e-10f);
    }
}

// ---------------------------------------------------------------------------
extern "C" void kernel_launch(void* const* d_in, const int* in_sizes, int n_in,
                              void* d_out, int out_size)
{
    (void)in_sizes; (void)n_in; (void)out_size;
    const float* ctx_val  = (const float*)d_in[0];
    const float* ctx_key  = (const float*)d_in[1];
    const float* ctx_mask = (const float*)d_in[2];
    const float* past     = (const float*)d_in[3];  // attention_past (B,1,L)
    const float* ht       = (const float*)d_in[4];
    const float* Wc       = (const float*)d_in[5];  // (512,1,3)
    const float* Wq       = (const float*)d_in[6];  // (256,256)
    const float* Wap      = (const float*)d_in[7];  // (256,512)
    const float* bap      = (const float*)d_in[8];  // (256,)
    const float* Wattn    = (const float*)d_in[9];  // (1,256)
    const float* battn    = (const float*)d_in[10]; // (1,)
    float* out = (float*)d_out;

    prep_kernel<<<HQ_BLOCKS + M_BLOCKS, 256>>>(ht, Wq, Wap, Wc, bap);

    dim3 grid(NCHUNK, BATCH);
    main_kernel<<<grid, 256>>>(ctx_val, ctx_key, ctx_mask, past, Wattn, battn);

    int total = BATCH * DDIM + L_MAX * BATCH;
    finish_kernel<<<(total + 255) / 256, 256>>>(out);
}